// round 6
// baseline (speedup 1.0000x reference)
#include <cuda_runtime.h>

#define EPSF 1e-5f
#define NB   128   // 128 blocks < 148 SMs -> all co-resident; per-batch barriers over 64 blocks

// Scratch (__device__ globals per allocation-free rule)
__device__ float2 g_xy[2 * 128 * 256];     // interleaved {xn, yn}, (b, c, hw)
__device__ float  g_s [2 * 128 * 256];     // s[b, o, i]
__device__ unsigned g_bar2[2] = {0, 0};
__device__ volatile unsigned g_gen2[2] = {0, 0};

// ---- packed f32x2 helpers ----
__device__ __forceinline__ unsigned long long pk2(float a, float b) {
    unsigned long long r;
    asm("mov.b64 %0, {%1, %2};" : "=l"(r) : "f"(a), "f"(b));
    return r;
}
__device__ __forceinline__ unsigned long long dup2(float a) {
    unsigned long long r;
    asm("mov.b64 %0, {%1, %1};" : "=l"(r) : "f"(a));
    return r;
}
__device__ __forceinline__ float2 upk2(unsigned long long v) {
    float a, b;
    asm("mov.b64 {%0, %1}, %2;" : "=f"(a), "=f"(b) : "l"(v));
    return make_float2(a, b);
}
__device__ __forceinline__ unsigned long long fma2(unsigned long long a,
                                                   unsigned long long b,
                                                   unsigned long long c) {
    unsigned long long r;
    asm("fma.rn.f32x2 %0, %1, %2, %3;" : "=l"(r) : "l"(a), "l"(b), "l"(c));
    return r;
}
__device__ __forceinline__ unsigned long long add2(unsigned long long a,
                                                   unsigned long long b) {
    unsigned long long r;
    asm("add.rn.f32x2 %0, %1, %2;" : "=l"(r) : "l"(a), "l"(b));
    return r;
}
__device__ __forceinline__ unsigned long long lds64(const float2* p) {
    return *(const unsigned long long*)p;
}

// Per-batch grid barrier over 64 blocks (generation-based; reusable across
// barriers and graph replays).
__device__ __forceinline__ void batch_barrier(int bb) {
    __syncthreads();
    if (threadIdx.x == 0) {
        __threadfence();
        unsigned gen = g_gen2[bb];
        if (atomicAdd(&g_bar2[bb], 1u) == 63u) {
            g_bar2[bb] = 0;
            __threadfence();
            g_gen2[bb] = gen + 1;
        } else {
            while (g_gen2[bb] == gen) { }
        }
    }
    __syncthreads();
}

// ---------------------------------------------------------------------------
// One persistent kernel, 128 blocks x 1024 threads (32 warps/SM).
// Groups of 256 threads: g = tid>>8 (0..3), j = tid&255, ch = g&1, h = g>>1.
//  phase 1: groups 0/1 -> x rows bid*2+{0,1} (+pos); groups 2/3 -> y rows.
//  phase 2: c-GEMV split 4 ways (packed f32x2 over channel pair o0,o0+1),
//           combine, separable inorm (b1 cancels; var = varA+varB),
//           relu-sum via s[i] = 128 b'_i + 0.5 sum_j |a'_j + b'_i|
//           (valid since sum_j a'_j = 0), j-split 2 ways per channel.
//  phase 3: o-loop split 4 ways (packed over output-channel pair), combine.
// ---------------------------------------------------------------------------
__global__ void __launch_bounds__(1024, 1)
rn_fused(const float* __restrict__ x, const float* __restrict__ y,
         const float* __restrict__ pos, const float* __restrict__ w1,
         const float* __restrict__ w2, const float* __restrict__ b2,
         float* __restrict__ out) {
    __shared__ __align__(16) float2 s_wA[128];    // {Wi_o0[c], Wi_o1[c]}
    __shared__ __align__(16) float2 s_wB[128];    // {Wj_o0[c], Wj_o1[c]}
    __shared__ __align__(16) float2 s_wY[128];    // {Wy_o0[c], Wy_o1[c]}
    __shared__ __align__(16) float2 s_w2p[128];   // {w2_p0[o], w2_p1[o]}
    __shared__ __align__(16) float  s_as[512];    // a' per channel (float4-read)
    __shared__ __align__(16) float2 s_pa[1024];   // packed partial exchange
    __shared__ __align__(16) float2 s_pb[1024];
    __shared__ __align__(16) float  s_ps[1024];   // relu partial exchange
    __shared__ __align__(16) float  s_red[128];
    __shared__ float s_b2[2];

    const int tid  = threadIdx.x;           // 0..1023
    const int g    = tid >> 8;               // group 0..3
    const int j    = tid & 255;
    const int lane = tid & 31;
    const int wid  = tid >> 5;               // 0..31
    const int ch   = g & 1;                  // channel within pair
    const int h    = g >> 1;                 // half index
    const int bid  = blockIdx.x;
    const int bb   = bid >> 6;                // batch
    const int o0   = (bid & 63) * 2;          // channel pair

    // ---- preload packed weights (first use after barrier / later phases) ----
    if (tid < 128) {
        const float* w1r = w1 + o0 * 384;
        s_wA[tid]  = make_float2(w1r[tid],       w1r[384 + tid]);
        s_wB[tid]  = make_float2(w1r[128 + tid], w1r[512 + tid]);
        s_wY[tid]  = make_float2(w1r[256 + tid], w1r[640 + tid]);
        const float* w2r = w2 + o0 * 128;
        s_w2p[tid] = make_float2(w2r[tid], w2r[128 + tid]);
    }
    if (tid < 2) s_b2[tid] = b2[o0 + tid];

    // ---- phase 1: one (tensor,row) per group ----
    {
        const int row = bid * 2 + ch;        // groups (0,2)->row0, (1,3)->row1
        float v;
        if (h == 0) v = x[row * 256 + j] + pos[j * 128 + (row & 127)];
        else        v = y[row * 256 + j];
        float s1 = v, s2 = v * v;
#pragma unroll
        for (int o = 16; o > 0; o >>= 1) {
            s1 += __shfl_down_sync(0xffffffffu, s1, o);
            s2 += __shfl_down_sync(0xffffffffu, s2, o);
        }
        if (lane == 0) { s_red[g * 32 + (wid & 7)] = s1; s_red[g * 32 + 8 + (wid & 7)] = s2; }
        __syncthreads();
        float t1 = 0.f, t2 = 0.f;
#pragma unroll
        for (int w = 0; w < 8; w++) { t1 += s_red[g * 32 + w]; t2 += s_red[g * 32 + 8 + w]; }
        const float inv = 1.f / 256.f;
        const float m = t1 * inv;
        const float r = rsqrtf(t2 * inv - m * m + EPSF);
        const float o_ = fmaxf((v - m) * r, 0.f);
        if (h == 0) g_xy[row * 256 + j].x = o_;
        else        g_xy[row * 256 + j].y = o_;
    }

    batch_barrier(bb);

    // ---- phase 2: relate for (bb, o0) and (bb, o0+1) ----
    {
        const float2* __restrict__ xy = g_xy + bb * 32768;
        unsigned long long accA = 0ull, accB = 0ull;   // packed (ch0, ch1)
        const int cbase = g * 32;
#pragma unroll 8
        for (int cc = 0; cc < 32; cc++) {
            const int c = cbase + cc;
            const float2 v = __ldcg(&xy[c * 256 + j]);
            const unsigned long long xx = dup2(v.x);
            const unsigned long long yy = dup2(v.y);
            accA = fma2(lds64(&s_wA[c]), xx, accA);
            accB = fma2(lds64(&s_wB[c]), xx, accB);
            accB = fma2(lds64(&s_wY[c]), yy, accB);
        }
        s_pa[tid] = upk2(accA);
        s_pb[tid] = upk2(accB);
        __syncthreads();

        // combine 4 partials; this thread owns channel ch at position j
        const float2 a0 = s_pa[j], a1 = s_pa[256 + j], a2 = s_pa[512 + j], a3 = s_pa[768 + j];
        const float2 b0 = s_pb[j], b1 = s_pb[256 + j], b2_ = s_pb[512 + j], b3 = s_pb[768 + j];
        const float A = ch ? (a0.y + a1.y + a2.y + a3.y) : (a0.x + a1.x + a2.x + a3.x);
        const float B = ch ? (b0.y + b1.y + b2_.y + b3.y) : (b0.x + b1.x + b2_.x + b3.x);

        // stats over 512 threads holding each channel (values duplicated x2 -> /512 exact)
        float sA = A, sA2 = A * A, sB = B, sB2 = B * B;
#pragma unroll
        for (int o = 16; o > 0; o >>= 1) {
            sA  += __shfl_down_sync(0xffffffffu, sA,  o);
            sA2 += __shfl_down_sync(0xffffffffu, sA2, o);
            sB  += __shfl_down_sync(0xffffffffu, sB,  o);
            sB2 += __shfl_down_sync(0xffffffffu, sB2, o);
        }
        if (lane == 0) {
            const int slot = h * 8 + (wid & 7);          // 0..15 within channel
            float* r = s_red + ch * 64;
            r[slot] = sA; r[16 + slot] = sA2; r[32 + slot] = sB; r[48 + slot] = sB2;
        }
        __syncthreads();
        const float* r = s_red + ch * 64;
        float tA = 0.f, tA2 = 0.f, tB = 0.f, tB2 = 0.f;
#pragma unroll
        for (int w = 0; w < 16; w++) {
            tA += r[w]; tA2 += r[16 + w]; tB += r[32 + w]; tB2 += r[48 + w];
        }
        const float inv = 1.f / 512.f;                    // duplicates folded in
        const float mA = tA * inv, mB = tB * inv;
        const float rs = rsqrtf((tA2 * inv - mA * mA) + (tB2 * inv - mB * mB) + EPSF);
        const float ap = (A - mA) * rs;
        const float bp = (B - mB) * rs;
        if (h == 0) s_as[ch * 256 + j] = ap;
        __syncthreads();

        // relu partial: half h sums q in [h*32, h*32+32)
        const unsigned long long bp2 = dup2(bp);
        float sabs = 0.f;
        const float4* a4 = (const float4*)(s_as + ch * 256);
#pragma unroll 8
        for (int q = h * 32; q < h * 32 + 32; q++) {
            const float4 u = a4[q];
            const float2 t0 = upk2(add2(pk2(u.x, u.y), bp2));
            const float2 t1 = upk2(add2(pk2(u.z, u.w), bp2));
            sabs += fabsf(t0.x); sabs += fabsf(t0.y);
            sabs += fabsf(t1.x); sabs += fabsf(t1.y);
        }
        s_ps[tid] = sabs;
        __syncthreads();

        if (g < 2) {   // g == ch, h == 0
            const float tot = s_ps[g * 256 + j] + s_ps[(g + 2) * 256 + j];
            g_s[(bb * 128 + o0 + g) * 256 + j] = fmaf(128.f, bp, 0.5f * tot);
        }
    }

    batch_barrier(bb);

    // ---- phase 3: out[bb, o0+{0,1}, :]; o-loop split 4 ways ----
    {
        const float* __restrict__ sr = g_s + bb * 32768;
        unsigned long long acc = 0ull;                   // packed (p0, p1)
        const int obase = g * 32;
#pragma unroll 8
        for (int oo = 0; oo < 32; oo++) {
            const int o = obase + oo;
            const float sv = __ldcg(&sr[o * 256 + j]);
            acc = fma2(lds64(&s_w2p[o]), dup2(sv), acc);
        }
        s_pa[tid] = upk2(acc);
        __syncthreads();

        if (g < 2) {
            const float2 p0 = s_pa[j], p1 = s_pa[256 + j],
                         p2 = s_pa[512 + j], p3 = s_pa[768 + j];
            const float v = g ? (p0.y + p1.y + p2.y + p3.y)
                              : (p0.x + p1.x + p2.x + p3.x);
            out[(bb * 128 + o0 + g) * 256 + j] = v + 256.f * s_b2[g];
        }
    }
}

extern "C" void kernel_launch(void* const* d_in, const int* in_sizes, int n_in,
                              void* d_out, int out_size) {
    const float* x   = (const float*)d_in[0];   // (2,128,16,16)
    const float* y   = (const float*)d_in[1];   // (2,128,16,16)
    const float* pos = (const float*)d_in[2];   // (256,128)
    const float* w1  = (const float*)d_in[3];   // (128,384)
    // d_in[4] = b1 — provably unused (cancels in instance-norm centering)
    const float* w2  = (const float*)d_in[5];   // (128,128)
    const float* b2  = (const float*)d_in[6];   // (128,)
    float* out = (float*)d_out;                 // (2,128,16,16)

    rn_fused<<<NB, 1024>>>(x, y, pos, w1, w2, b2, out);
}

// round 7
// speedup vs baseline: 1.0968x; 1.0968x over previous
#include <cuda_runtime.h>

#define EPSF 1e-5f
#define NB   128   // 128 blocks < 148 SMs -> co-resident; per-batch barriers over 64 blocks

// Scratch (__device__ globals per allocation-free rule)
__device__ float4 g_xy4[2 * 64 * 256];    // [b][c/2][j] = {x(c0),y(c0),x(c1),y(c1)} normalized
__device__ float2 g_s2 [2 * 64 * 256];    // [b][o/2][j] = {s(o0), s(o1)}
__device__ unsigned g_bar2[2] = {0, 0};
__device__ volatile unsigned g_gen2[2] = {0, 0};

// ---- packed f32x2 helpers ----
__device__ __forceinline__ unsigned long long pk2(float a, float b) {
    unsigned long long r;
    asm("mov.b64 %0, {%1, %2};" : "=l"(r) : "f"(a), "f"(b));
    return r;
}
__device__ __forceinline__ unsigned long long dup2(float a) {
    unsigned long long r;
    asm("mov.b64 %0, {%1, %1};" : "=l"(r) : "f"(a));
    return r;
}
__device__ __forceinline__ float2 upk2(unsigned long long v) {
    float a, b;
    asm("mov.b64 {%0, %1}, %2;" : "=f"(a), "=f"(b) : "l"(v));
    return make_float2(a, b);
}
__device__ __forceinline__ unsigned long long fma2(unsigned long long a,
                                                   unsigned long long b,
                                                   unsigned long long c) {
    unsigned long long r;
    asm("fma.rn.f32x2 %0, %1, %2, %3;" : "=l"(r) : "l"(a), "l"(b), "l"(c));
    return r;
}
__device__ __forceinline__ unsigned long long add2(unsigned long long a,
                                                   unsigned long long b) {
    unsigned long long r;
    asm("add.rn.f32x2 %0, %1, %2;" : "=l"(r) : "l"(a), "l"(b));
    return r;
}
__device__ __forceinline__ unsigned long long lds64(const float2* p) {
    return *(const unsigned long long*)p;
}

// Per-batch grid barrier over 64 blocks (generation-based, graph-replay safe).
__device__ __forceinline__ void batch_barrier(int bb) {
    __syncthreads();
    if (threadIdx.x == 0) {
        __threadfence();
        unsigned gen = g_gen2[bb];
        if (atomicAdd(&g_bar2[bb], 1u) == 63u) {
            g_bar2[bb] = 0;
            __threadfence();
            g_gen2[bb] = gen + 1;
        } else {
            while (g_gen2[bb] == gen) { }
        }
    }
    __syncthreads();
}

// Group-wide (256-thread) reduction of 4 values; two groups reduce concurrently
// in disjoint smem slices. All 512 threads must reach the syncs.
__device__ __forceinline__ void red4g(float a, float b, float c, float d,
                                      float* red /*[64]*/, float out[4],
                                      int lane, int gwid, int ch) {
#pragma unroll
    for (int o = 16; o > 0; o >>= 1) {
        a += __shfl_down_sync(0xffffffffu, a, o);
        b += __shfl_down_sync(0xffffffffu, b, o);
        c += __shfl_down_sync(0xffffffffu, c, o);
        d += __shfl_down_sync(0xffffffffu, d, o);
    }
    __syncthreads();
    if (lane == 0) {
        float* r = red + ch * 32;
        r[gwid] = a; r[8 + gwid] = b; r[16 + gwid] = c; r[24 + gwid] = d;
    }
    __syncthreads();
    const float* r = red + ch * 32;
    float t0 = 0.f, t1 = 0.f, t2 = 0.f, t3 = 0.f;
#pragma unroll
    for (int w = 0; w < 8; w++) {
        t0 += r[w]; t1 += r[8 + w]; t2 += r[16 + w]; t3 += r[24 + w];
    }
    out[0] = t0; out[1] = t1; out[2] = t2; out[3] = t3;
}

// ---------------------------------------------------------------------------
// One persistent kernel, 128 blocks x 512 threads (R5 structure + packed I/O).
//  phase 1: group g normalizes row bid*2+g of x (+pos) and y; odd group passes
//           its pair through smem; group 0 writes one float4 per j -> g_xy4
//  phase 2: c-pair GEMV split 2 ways (LDG.128; packed f32x2 over channel pair),
//           separable inorm (b1 cancels; var = varA+varB),
//           s[i] = 128 b'_i + 0.5 sum_j |a'_j + b'_i|  (sum_j a'_j = 0),
//           packed-abs accumulation; store paired float2 -> g_s2
//  phase 3: o-pair loop split 2 ways (LDG.64; packed over output-channel pair)
// ---------------------------------------------------------------------------
__global__ void __launch_bounds__(512, 1)
rn_fused(const float* __restrict__ x, const float* __restrict__ y,
         const float* __restrict__ pos, const float* __restrict__ w1,
         const float* __restrict__ w2, const float* __restrict__ b2,
         float* __restrict__ out) {
    __shared__ __align__(16) float2 s_wA[128];    // {Wi_o0[c], Wi_o1[c]}
    __shared__ __align__(16) float2 s_wB[128];    // {Wj_o0[c], Wj_o1[c]}
    __shared__ __align__(16) float2 s_wY[128];    // {Wy_o0[c], Wy_o1[c]}
    __shared__ __align__(16) float2 s_w2p[128];   // {w2_p0[o], w2_p1[o]}
    __shared__ __align__(16) float  s_as[512];    // a' per channel (float4-read)
    __shared__ __align__(16) float2 s_pa[512];    // packed partial exchange
    __shared__ __align__(16) float2 s_pb[512];
    __shared__ __align__(16) float  s_red[64];
    __shared__ float s_b2[2];

    const int tid  = threadIdx.x;          // 0..511
    const int g    = tid >> 8;             // group 0/1
    const int j    = tid & 255;
    const int lane = tid & 31;
    const int gwid = (tid >> 5) & 7;
    const int bid  = blockIdx.x;
    const int bb   = bid >> 6;             // batch
    const int o0   = (bid & 63) * 2;       // channel pair

    // ---- preload packed weights (first use after batch_barrier) ----
    if (tid < 128) {
        const float* w1r = w1 + o0 * 384;
        s_wA[tid]  = make_float2(w1r[tid],       w1r[384 + tid]);
        s_wB[tid]  = make_float2(w1r[128 + tid], w1r[512 + tid]);
        s_wY[tid]  = make_float2(w1r[256 + tid], w1r[640 + tid]);
        const float* w2r = w2 + o0 * 128;
        s_w2p[tid] = make_float2(w2r[tid], w2r[128 + tid]);
    }
    if (tid < 2) s_b2[tid] = b2[o0 + tid];

    // ---- phase 1: group g normalizes row idx = bid*2+g (x with pos, and y) ----
    {
        const int idx = bid * 2 + g;
        const int c   = idx & 127;
        float xv = x[idx * 256 + j] + pos[j * 128 + c];
        float yv = y[idx * 256 + j];
        float r[4];
        red4g(xv, xv * xv, yv, yv * yv, s_red, r, lane, gwid, g);
        const float inv = 1.f / 256.f;
        const float mx = r[0] * inv, my = r[2] * inv;
        const float rx = rsqrtf(r[1] * inv - mx * mx + EPSF);
        const float ry = rsqrtf(r[3] * inv - my * my + EPSF);
        const float xn = fmaxf((xv - mx) * rx, 0.f);
        const float yn = fmaxf((yv - my) * ry, 0.f);
        if (g == 1) s_pa[j] = make_float2(xn, yn);
        __syncthreads();
        if (g == 0) {
            const float2 hi = s_pa[j];
            g_xy4[bid * 256 + j] = make_float4(xn, yn, hi.x, hi.y);
        }
    }

    batch_barrier(bb);

    // ---- phase 2: relate for (bb, o0) and (bb, o0+1) ----
    {
        const float4* __restrict__ xy = g_xy4 + bb * 16384;
        unsigned long long accA = 0ull, accB = 0ull;   // packed (ch0, ch1)
        const int pbase = g * 32;                      // c-pair range
#pragma unroll 8
        for (int pp = 0; pp < 32; pp++) {
            const int cp = pbase + pp;
            const float4 v = __ldcg(&xy[cp * 256 + j]);
            const int c0 = cp * 2;
            accA = fma2(lds64(&s_wA[c0]),     dup2(v.x), accA);
            accB = fma2(lds64(&s_wB[c0]),     dup2(v.x), accB);
            accB = fma2(lds64(&s_wY[c0]),     dup2(v.y), accB);
            accA = fma2(lds64(&s_wA[c0 + 1]), dup2(v.z), accA);
            accB = fma2(lds64(&s_wB[c0 + 1]), dup2(v.z), accB);
            accB = fma2(lds64(&s_wY[c0 + 1]), dup2(v.w), accB);
        }
        s_pa[tid] = upk2(accA);
        s_pb[tid] = upk2(accB);
        __syncthreads();

        // combine group partials; group index now selects output channel g
        float A, B;
        if (g == 0) { A = s_pa[j].x + s_pa[256 + j].x; B = s_pb[j].x + s_pb[256 + j].x; }
        else        { A = s_pa[j].y + s_pa[256 + j].y; B = s_pb[j].y + s_pb[256 + j].y; }

        float r[4];
        red4g(A, A * A, B, B * B, s_red, r, lane, gwid, g);
        const float inv = 1.f / 256.f;
        const float mA = r[0] * inv, mB = r[2] * inv;
        const float rs = rsqrtf((r[1] * inv - mA * mA) + (r[3] * inv - mB * mB) + EPSF);
        s_as[g * 256 + j] = (A - mA) * rs;
        const float bp  = (B - mB) * rs;
        __syncthreads();

        // s[i] = 128*bp + 0.5 * sum_j |a'_j + bp|   (packed abs via mask)
        const unsigned long long bp2  = dup2(bp);
        const unsigned long long ABS2 = 0x7FFFFFFF7FFFFFFFull;
        unsigned long long sabs2 = 0ull;
        const float4* a4 = (const float4*)(s_as + g * 256);
#pragma unroll 8
        for (int q = 0; q < 64; q++) {
            const float4 u = a4[q];
            sabs2 = add2(sabs2, add2(pk2(u.x, u.y), bp2) & ABS2);
            sabs2 = add2(sabs2, add2(pk2(u.z, u.w), bp2) & ABS2);
        }
        const float2 sv = upk2(sabs2);
        const float s_val = fmaf(128.f, bp, 0.5f * (sv.x + sv.y));
        ((float*)&g_s2[bid * 256 + j])[g] = s_val;   // paired store {s_o0, s_o1}
    }

    batch_barrier(bb);

    // ---- phase 3: out[bb, o0+{0,1}, :]; o-pair loop split 2 ways ----
    {
        const float2* __restrict__ sr = g_s2 + bb * 16384;
        unsigned long long acc = 0ull;                 // packed (p0, p1)
        const int kbase = g * 32;
#pragma unroll 8
        for (int kk = 0; kk < 32; kk++) {
            const int k = kbase + kk;
            const float2 sv = __ldcg(&sr[k * 256 + j]);
            acc = fma2(lds64(&s_w2p[2 * k]),     dup2(sv.x), acc);
            acc = fma2(lds64(&s_w2p[2 * k + 1]), dup2(sv.y), acc);
        }
        s_pa[tid] = upk2(acc);
        __syncthreads();

        const float part = (g == 0) ? (s_pa[j].x + s_pa[256 + j].x)
                                    : (s_pa[j].y + s_pa[256 + j].y);
        out[(bb * 128 + o0 + g) * 256 + j] = part + 256.f * s_b2[g];
    }
}

extern "C" void kernel_launch(void* const* d_in, const int* in_sizes, int n_in,
                              void* d_out, int out_size) {
    const float* x   = (const float*)d_in[0];   // (2,128,16,16)
    const float* y   = (const float*)d_in[1];   // (2,128,16,16)
    const float* pos = (const float*)d_in[2];   // (256,128)
    const float* w1  = (const float*)d_in[3];   // (128,384)
    // d_in[4] = b1 — provably unused (cancels in instance-norm centering)
    const float* w2  = (const float*)d_in[5];   // (128,128)
    const float* b2  = (const float*)d_in[6];   // (128,)
    float* out = (float*)d_out;                 // (2,128,16,16)

    rn_fused<<<NB, 512>>>(x, y, pos, w1, w2, b2, out);
}